// round 5
// baseline (speedup 1.0000x reference)
#include <cuda_runtime.h>
#include <cstdint>

#define NPTS   16384
#define NPOINT 1024
#define NBATCH 4
#define NTHR   512
#define NWARP  (NTHR / 32)
#define CHUNKS 8                 // float4 chunks per thread
#define PPT    (CHUNKS * 4)      // 32 points per thread

// ---------------------------------------------------------------------------
// Block-wide argmax, first-occurrence (smallest index) tie-break.
// ---------------------------------------------------------------------------
__device__ __forceinline__ int block_argmax(float v, int i,
                                            float* rv, int* ri, int* s_far) {
    #pragma unroll
    for (int off = 16; off > 0; off >>= 1) {
        float ov = __shfl_down_sync(0xffffffffu, v, off);
        int   oi = __shfl_down_sync(0xffffffffu, i, off);
        if (ov > v || (ov == v && oi < i)) { v = ov; i = oi; }
    }
    const int warp = threadIdx.x >> 5;
    const int lane = threadIdx.x & 31;
    if (lane == 0) { rv[warp] = v; ri[warp] = i; }
    __syncthreads();
    if (warp == 0) {
        if (lane < NWARP) { v = rv[lane]; i = ri[lane]; }
        else              { v = -3.402823466e38f; i = 0x7FFFFFFF; }
        #pragma unroll
        for (int off = 8; off > 0; off >>= 1) {
            float ov = __shfl_down_sync(0xffffffffu, v, off);
            int   oi = __shfl_down_sync(0xffffffffu, i, off);
            if (ov > v || (ov == v && oi < i)) { v = ov; i = oi; }
        }
        if (lane == 0) *s_far = i;
    }
    __syncthreads();
    return *s_far;
}

// ---------------------------------------------------------------------------
// Fused FPS + ball query. One CTA per batch. xyz layout [B,3,N].
// FP semantics mirror XLA's FMA contraction:
//   FPS:  d = fma(dz,dz, fma(dy,dy, dx*dx)),  dist = min(dist, d)
//   ball: dot = fma(z,z', fma(y,y', x*x')),  d = fma(-2,dot,|s|^2) + |t|^2
// First-occurrence argmax; records PRE-update farthest each step.
// OUTPUT IS WRITTEN AS FLOAT32 (indices as float values).
// ---------------------------------------------------------------------------
__global__ void __launch_bounds__(NTHR, 1)
fused_kernel(const float* __restrict__ xyz, float* __restrict__ out) {
    __shared__ int   s_cent[NPOINT];
    __shared__ float rv[NWARP];
    __shared__ int   ri[NWARP];
    __shared__ int   s_far;

    const int b    = blockIdx.x;
    const int tid  = threadIdx.x;
    const int warp = tid >> 5;
    const int lane = tid & 31;

    const float* __restrict__ base = xyz + (size_t)b * 3 * NPTS;
    const float4* __restrict__ X4 = (const float4*)base;
    const float4* __restrict__ Y4 = X4 + NPTS / 4;
    const float4* __restrict__ Z4 = Y4 + NPTS / 4;

    // ================= phase 1: farthest point sampling =================
    // initial farthest = argmax over x (exact comparisons, first occurrence)
    float bv = -3.402823466e38f; int bi = 0x7FFFFFFF;
    #pragma unroll
    for (int c = 0; c < CHUNKS; c++) {
        const float4 X = __ldg(&X4[c * NTHR + tid]);
        const int p = (c * NTHR + tid) * 4;
        if (X.x > bv) { bv = X.x; bi = p;     }
        if (X.y > bv) { bv = X.y; bi = p + 1; }
        if (X.z > bv) { bv = X.z; bi = p + 2; }
        if (X.w > bv) { bv = X.w; bi = p + 3; }
    }
    int far = block_argmax(bv, bi, rv, ri, &s_far);

    float dist[PPT];
    #pragma unroll
    for (int i = 0; i < PPT; i++) dist[i] = 1e10f;

    for (int k = 0; k < NPOINT; k++) {
        if (tid == 0) s_cent[k] = far;

        const float cx = __ldg(&base[far]);
        const float cy = __ldg(&base[NPTS + far]);
        const float cz = __ldg(&base[2 * NPTS + far]);

        float mv = -1.0f; int mi = 0x7FFFFFFF;
        #pragma unroll
        for (int c = 0; c < CHUNKS; c++) {
            const float4 X = __ldg(&X4[c * NTHR + tid]);
            const float4 Y = __ldg(&Y4[c * NTHR + tid]);
            const float4 Z = __ldg(&Z4[c * NTHR + tid]);
            const int p = (c * NTHR + tid) * 4;
            const float xs[4] = {X.x, X.y, X.z, X.w};
            const float ys[4] = {Y.x, Y.y, Y.z, Y.w};
            const float zs[4] = {Z.x, Z.y, Z.z, Z.w};
            #pragma unroll
            for (int e = 0; e < 4; e++) {
                const float dx = __fsub_rn(xs[e], cx);
                const float dy = __fsub_rn(ys[e], cy);
                const float dz = __fsub_rn(zs[e], cz);
                const float d  = __fmaf_rn(dz, dz,
                                 __fmaf_rn(dy, dy, __fmul_rn(dx, dx)));
                const float dd = fminf(dist[c * 4 + e], d);
                dist[c * 4 + e] = dd;
                if (dd > mv) { mv = dd; mi = p + e; }  // strict >: first occurrence
            }
        }
        far = block_argmax(mv, mi, rv, ri, &s_far);
    }
    __syncthreads();   // s_cent fully written

    // ================= phase 2: ball query (one warp per centroid) ========
    for (int s = warp; s < NPOINT; s += NWARP) {
        const int c = s_cent[s];
        const float xs = __ldg(&base[c]);
        const float ys = __ldg(&base[NPTS + c]);
        const float zs = __ldg(&base[2 * NPTS + c]);
        const float snorm = __fmaf_rn(zs, zs,
                            __fmaf_rn(ys, ys, __fmul_rn(xs, xs)));

        int winner = NPTS;  // reference keeps N when nothing qualifies
        for (int j0 = 0; j0 < NPTS; j0 += 32) {
            const int j = j0 + lane;
            const float xj = __ldg(&base[j]);
            const float yj = __ldg(&base[NPTS + j]);
            const float zj = __ldg(&base[2 * NPTS + j]);
            const float dot   = __fmaf_rn(zs, zj,
                                __fmaf_rn(ys, yj, __fmul_rn(xs, xj)));
            const float dnorm = __fmaf_rn(zj, zj,
                                __fmaf_rn(yj, yj, __fmul_rn(xj, xj)));
            const float d = __fadd_rn(__fmaf_rn(-2.0f, dot, snorm), dnorm);
            const unsigned m = __ballot_sync(0xffffffffu, !(d > 0.25f));
            if (m) { winner = j0 + __ffs(m) - 1; break; }
        }
        // output dtype experiment: write indices as FLOAT32
        if (lane == 0) out[b * NPOINT + s] = (float)winner;
    }
}

// ---------------------------------------------------------------------------
extern "C" void kernel_launch(void* const* d_in, const int* in_sizes, int n_in,
                              void* d_out, int out_size) {
    // identify xyz robustly by element count (4*3*16384 = 196608)
    int xi = 0;
    for (int i = 0; i < n_in; i++) {
        if (in_sizes[i] == NBATCH * 3 * NPTS) { xi = i; break; }
    }
    const float* xyz = (const float*)d_in[xi];
    float* out = (float*)d_out;

    fused_kernel<<<NBATCH, NTHR>>>(xyz, out);
}

// round 8
// speedup vs baseline: 1.0353x; 1.0353x over previous
#include <cuda_runtime.h>
#include <cstdint>

#define NPTS   16384
#define NPOINT 1024
#define NBATCH 4
#define CSIZE  4                  // CTAs cooperating per batch
#define NTHR   512
#define NWARP  16
#define PPT    8                  // register-resident points per thread
#define NROUND 1024               // sync rounds: r=0 initial, r=1..1023

// write-once-per-round key slots; replay-safe because every run rewrites
// bit-identical values (deterministic) and tag 0 never matches a real tag.
__device__ unsigned long long g_key[NBATCH][NROUND][CSIZE];

// key = bits(dist)<<32 | (~idx & 0x3FFF)<<11 | tag   (tag = r+1, 1..1024)
__device__ __forceinline__ unsigned long long pack_key(float v, int idx,
                                                       unsigned tag) {
    return ((unsigned long long)__float_as_uint(v) << 32)
         | (unsigned)((((~idx) & 0x3FFF) << 11) | tag);
}
__device__ __forceinline__ int key_idx(unsigned long long k) {
    return (~((unsigned)(k >> 11))) & 0x3FFF;
}

// ---------------------------------------------------------------------------
// Cross-CTA argmax: block shfl/smem reduce -> release-store own slot ->
// lanes 0..3 spin on the 4 slots (tag match) -> max -> broadcast via smem.
// ---------------------------------------------------------------------------
__device__ __forceinline__ int sync_argmax(unsigned long long key,
                                           int b, int r, uint32_t rank,
                                           unsigned long long* s_wred,
                                           int* s_far) {
    const int tid  = threadIdx.x;
    const int warp = tid >> 5;
    const int lane = tid & 31;
    const unsigned tag = (unsigned)(r + 1);

    #pragma unroll
    for (int off = 16; off > 0; off >>= 1) {
        unsigned long long o = __shfl_down_sync(0xffffffffu, key, off);
        if (o > key) key = o;
    }
    if (lane == 0) s_wred[warp] = key;
    __syncthreads();

    if (warp == 0) {
        unsigned long long k2 = s_wred[lane & (NWARP - 1)];
        #pragma unroll
        for (int off = 8; off > 0; off >>= 1) {
            unsigned long long o = __shfl_down_sync(0xffffffffu, k2, off);
            if (o > k2) k2 = o;
        }
        if (lane == 0) {
            unsigned long long* p = &g_key[b][r][rank];
            asm volatile("st.release.gpu.global.u64 [%0], %1;"
                         :: "l"(p), "l"(k2) : "memory");
        }
        unsigned long long kj = 0ULL;
        if (lane < CSIZE) {
            const unsigned long long* p = &g_key[b][r][lane];
            do {
                asm volatile("ld.acquire.gpu.global.u64 %0, [%1];"
                             : "=l"(kj) : "l"(p) : "memory");
            } while ((unsigned)(kj & 0x7FFu) != tag);
        }
        #pragma unroll
        for (int off = 2; off > 0; off >>= 1) {
            unsigned long long o = __shfl_down_sync(0xffffffffu, kj, off);
            if (o > kj) kj = o;
        }
        if (lane == 0) *s_far = key_idx(kj);
    }
    __syncthreads();
    return *s_far;
}

// ---------------------------------------------------------------------------
// Fused FPS + ball query. 4 cooperating CTAs per batch (plain launch, no
// clusters). Each CTA owns 4096 points in registers. FP semantics identical
// to the validated round-5 kernel; float32 output.
// ---------------------------------------------------------------------------
__global__ void __launch_bounds__(NTHR, 1)
fps_mc_kernel(const float* __restrict__ xyz, float* __restrict__ out) {
    __shared__ unsigned long long s_wred[NWARP];
    __shared__ int s_cent[NPOINT];
    __shared__ int s_far;

    const int tid  = threadIdx.x;
    const int warp = tid >> 5;
    const int lane = tid & 31;
    const int b    = blockIdx.x >> 2;
    const uint32_t rank = (uint32_t)(blockIdx.x & 3);

    const float* __restrict__ base = xyz + (size_t)b * 3 * NPTS;
    const float4* __restrict__ X4 = (const float4*)base;
    const float4* __restrict__ Y4 = X4 + NPTS / 4;
    const float4* __restrict__ Z4 = Y4 + NPTS / 4;

    // ---- load this CTA's 8 points/thread into registers ----
    float px[PPT], py[PPT], pz[PPT], dist[PPT];
    #pragma unroll
    for (int c = 0; c < 2; c++) {
        const int f4 = (int)rank * 1024 + c * NTHR + tid;
        const float4 X = __ldg(&X4[f4]);
        const float4 Y = __ldg(&Y4[f4]);
        const float4 Z = __ldg(&Z4[f4]);
        px[c*4+0] = X.x; px[c*4+1] = X.y; px[c*4+2] = X.z; px[c*4+3] = X.w;
        py[c*4+0] = Y.x; py[c*4+1] = Y.y; py[c*4+2] = Y.z; py[c*4+3] = Y.w;
        pz[c*4+0] = Z.x; pz[c*4+1] = Z.y; pz[c*4+2] = Z.z; pz[c*4+3] = Z.w;
    }
    const int pb = ((int)rank * 1024 + tid) * 4;  // chunk0 base; chunk1 = +2048
    #pragma unroll
    for (int i = 0; i < PPT; i++) dist[i] = 1e10f;

    // ---- round 0: argmax over x (first occurrence) ----
    int far;
    {
        float mv = -3.402823466e38f; int mi = 0;
        #pragma unroll
        for (int i = 0; i < PPT; i++) {
            const int p = ((i < 4) ? pb : (pb + 2048)) + (i & 3);
            if (px[i] > mv) { mv = px[i]; mi = p; }
        }
        far = sync_argmax(pack_key(mv, mi, 1u), b, 0, rank, s_wred, &s_far);
    }

    // ---- FPS main loop ----
    for (int k = 0; k < NPOINT; k++) {
        if (tid == 0) s_cent[k] = far;
        if (k == NPOINT - 1) break;

        const float cx = __ldg(&base[far]);
        const float cy = __ldg(&base[NPTS + far]);
        const float cz = __ldg(&base[2 * NPTS + far]);

        float mv = -1.0f; int mi = 0;
        #pragma unroll
        for (int i = 0; i < PPT; i++) {
            const float dx = __fsub_rn(px[i], cx);
            const float dy = __fsub_rn(py[i], cy);
            const float dz = __fsub_rn(pz[i], cz);
            const float d  = __fmaf_rn(dz, dz,
                             __fmaf_rn(dy, dy, __fmul_rn(dx, dx)));
            const float dd = fminf(dist[i], d);
            dist[i] = dd;
            if (dd > mv) {
                mv = dd;
                mi = ((i < 4) ? pb : (pb + 2048)) + (i & 3);
            }
        }
        far = sync_argmax(pack_key(mv, mi, (unsigned)(k + 2)),
                          b, k + 1, rank, s_wred, &s_far);
    }
    __syncthreads();   // s_cent complete (every CTA has full copy)

    // ---- ball query: this CTA handles 256 of the 1024 centroids ----
    const int gw = (int)rank * NWARP + warp;            // 0..63 per batch
    for (int t = 0; t < NPOINT / (CSIZE * NWARP); t++) {
        const int s = t * (CSIZE * NWARP) + gw;
        const int c = s_cent[s];
        const float xs = __ldg(&base[c]);
        const float ys = __ldg(&base[NPTS + c]);
        const float zs = __ldg(&base[2 * NPTS + c]);
        const float snorm = __fmaf_rn(zs, zs,
                            __fmaf_rn(ys, ys, __fmul_rn(xs, xs)));

        int winner = NPTS;
        for (int j0 = 0; j0 < NPTS; j0 += 32) {
            const int j = j0 + lane;
            const float xj = __ldg(&base[j]);
            const float yj = __ldg(&base[NPTS + j]);
            const float zj = __ldg(&base[2 * NPTS + j]);
            const float dot   = __fmaf_rn(zs, zj,
                                __fmaf_rn(ys, yj, __fmul_rn(xs, xj)));
            const float dnorm = __fmaf_rn(zj, zj,
                                __fmaf_rn(yj, yj, __fmul_rn(xj, xj)));
            const float d = __fadd_rn(__fmaf_rn(-2.0f, dot, snorm), dnorm);
            const unsigned m = __ballot_sync(0xffffffffu, !(d > 0.25f));
            if (m) { winner = j0 + __ffs(m) - 1; break; }
        }
        if (lane == 0) out[b * NPOINT + s] = (float)winner;
    }
}

// ---------------------------------------------------------------------------
extern "C" void kernel_launch(void* const* d_in, const int* in_sizes, int n_in,
                              void* d_out, int out_size) {
    int xi = 0;
    for (int i = 0; i < n_in; i++) {
        if (in_sizes[i] == NBATCH * 3 * NPTS) { xi = i; break; }
    }
    const float* xyz = (const float*)d_in[xi];
    float* out = (float*)d_out;

    fps_mc_kernel<<<NBATCH * CSIZE, NTHR>>>(xyz, out);
}